// round 10
// baseline (speedup 1.0000x reference)
#include <cuda_runtime.h>
#include <math.h>

// ---------------------------------------------------------------------------
// MultiScaleAdaptiveElasticityLossWithLame
//   d_in[0]: deformation_field (2,3,160,192,160) f32
//   d_in[1]: image             (2,1,160,192,160) f32
//   out: scalar f32 loss
// ---------------------------------------------------------------------------

#define D0 160
#define H0 192
#define W0 160
#define D1 80
#define H1 96
#define W1 80
#define D2 40
#define H2 48
#define W2 40

#define VOL0 (D0*H0*W0)
#define VOL1 (D1*H1*W1)
#define VOL2 (D2*H2*W2)

__device__ float g_def1[2*3*VOL1];
__device__ float g_img1[2*1*VOL1];
__device__ float g_def2[2*3*VOL2];
__device__ float g_img2[2*1*VOL2];
__device__ double g_acc[3];

__global__ void init_acc_kernel() {
    if (threadIdx.x < 3) g_acc[threadIdx.x] = 0.0;
}

// ---------------------------------------------------------------------------
// Fused trilinear downsample (align_corners=True): def (6 planes) + img (2).
// One output per thread; index decomposition entirely from grid/block dims.
template<int Di, int Hi, int Wi, int Do, int Ho, int Wo>
__global__ void downsample_both(const float* __restrict__ def,
                                const float* __restrict__ img,
                                float* __restrict__ odef,
                                float* __restrict__ oimg,
                                float rD, float rH, float rW)
{
    constexpr int OVOL = Do * Ho * Wo;
    constexpr int IVOL = Di * Hi * Wi;

    int x = threadIdx.x;
    int y = blockIdx.x * blockDim.y + threadIdx.y;
    int z = blockIdx.y;
    int p = blockIdx.z;            // 0..7

    const float* in; float* outp;
    if (p < 6) { in = def + p * IVOL;       outp = odef + p * OVOL; }
    else       { in = img + (p - 6) * IVOL; outp = oimg + (p - 6) * OVOL; }

    float cz = (float)z * rD;
    float cy = (float)y * rH;
    float cx = (float)x * rW;
    int z0 = min((int)floorf(cz), Di - 1);
    int y0 = min((int)floorf(cy), Hi - 1);
    int x0 = min((int)floorf(cx), Wi - 1);
    float wz = cz - (float)z0;
    float wy = cy - (float)y0;
    float wx = cx - (float)x0;
    int z1 = min(z0 + 1, Di - 1);
    int y1 = min(y0 + 1, Hi - 1);
    int x1 = min(x0 + 1, Wi - 1);

    const float* pz0 = in + z0 * (Hi * Wi);
    const float* pz1 = in + z1 * (Hi * Wi);
    int oy0 = y0 * Wi, oy1 = y1 * Wi;

    float v000 = __ldg(pz0 + oy0 + x0), v001 = __ldg(pz0 + oy0 + x1);
    float v010 = __ldg(pz0 + oy1 + x0), v011 = __ldg(pz0 + oy1 + x1);
    float v100 = __ldg(pz1 + oy0 + x0), v101 = __ldg(pz1 + oy0 + x1);
    float v110 = __ldg(pz1 + oy1 + x0), v111 = __ldg(pz1 + oy1 + x1);

    float a00 = v000 * (1.f - wx) + v001 * wx;
    float a01 = v010 * (1.f - wx) + v011 * wx;
    float a10 = v100 * (1.f - wx) + v101 * wx;
    float a11 = v110 * (1.f - wx) + v111 * wx;
    float b0 = a00 * (1.f - wy) + a01 * wy;
    float b1 = a10 * (1.f - wy) + a11 * wy;
    outp[z * (Ho * Wo) + y * Wo + x] = b0 * (1.f - wz) + b1 * wz;
}

__device__ __forceinline__ float4 f4add(float4 a, float4 b) {
    return make_float4(a.x + b.x, a.y + b.y, a.z + b.z, a.w + b.w);
}

// ---------------------------------------------------------------------------
// Gradients of one field at 4 consecutive W positions for TWO adjacent
// d-planes (d0, d0+1), sharing the 4 d-direction loads (vm,c0,c1,vp).
// Per field: 8 float4 + <=4 scalar loads for 8 outputs (vs 12+4 unshared).
template<int D, int H, int W>
__device__ __forceinline__ void field_grads2(const float* __restrict__ f,
                                             int d0, int h, int w,
                                             float4 gD[2], float4 gH[2], float4 gW_[2])
{
    constexpr int sH = W;
    constexpr int sD = H * W;
    const float* p0 = f + d0 * sD + h * sH + w;    // plane d0 row
    const float* p1 = p0 + sD;                     // plane d0+1 row

    float4 c0 = __ldg(reinterpret_cast<const float4*>(p0));
    float4 c1 = __ldg(reinterpret_cast<const float4*>(p1));
    float4 vm = __ldg(reinterpret_cast<const float4*>(p0 - (d0 > 0 ? sD : 0)));
    float4 vp = __ldg(reinterpret_cast<const float4*>(p1 + (d0 + 1 < D - 1 ? sD : 0)));

    // D gradients
    if (d0 == 0) {
        gD[0] = make_float4(c1.x - c0.x, c1.y - c0.y, c1.z - c0.z, c1.w - c0.w);
    } else {
        gD[0] = make_float4(0.5f * (c1.x - vm.x), 0.5f * (c1.y - vm.y),
                            0.5f * (c1.z - vm.z), 0.5f * (c1.w - vm.w));
    }
    if (d0 + 1 == D - 1) {
        gD[1] = make_float4(c1.x - c0.x, c1.y - c0.y, c1.z - c0.z, c1.w - c0.w);
    } else {
        gD[1] = make_float4(0.5f * (vp.x - c0.x), 0.5f * (vp.y - c0.y),
                            0.5f * (vp.z - c0.z), 0.5f * (vp.w - c0.w));
    }

    // H gradients (per plane)
    int hmD = (h > 0     ? -sH : 0);
    int hpD = (h < H - 1 ?  sH : 0);
    float sh = (h == 0 || h == H - 1) ? 1.0f : 0.5f;
    {
        float4 hm = __ldg(reinterpret_cast<const float4*>(p0 + hmD));
        float4 hp = __ldg(reinterpret_cast<const float4*>(p0 + hpD));
        gH[0] = make_float4(sh * (hp.x - hm.x), sh * (hp.y - hm.y),
                            sh * (hp.z - hm.z), sh * (hp.w - hm.w));
    }
    {
        float4 hm = __ldg(reinterpret_cast<const float4*>(p1 + hmD));
        float4 hp = __ldg(reinterpret_cast<const float4*>(p1 + hpD));
        gH[1] = make_float4(sh * (hp.x - hm.x), sh * (hp.y - hm.y),
                            sh * (hp.z - hm.z), sh * (hp.w - hm.w));
    }

    // W gradients (per plane)
    {
        float xl = (w > 0)     ? __ldg(p0 - 1) : 0.f;
        float xr = (w + 4 < W) ? __ldg(p0 + 4) : 0.f;
        gW_[0].x = (w == 0)     ? (c0.y - c0.x) : 0.5f * (c0.y - xl);
        gW_[0].y = 0.5f * (c0.z - c0.x);
        gW_[0].z = 0.5f * (c0.w - c0.y);
        gW_[0].w = (w + 4 == W) ? (c0.w - c0.z) : 0.5f * (xr - c0.z);
    }
    {
        float xl = (w > 0)     ? __ldg(p1 - 1) : 0.f;
        float xr = (w + 4 < W) ? __ldg(p1 + 4) : 0.f;
        gW_[1].x = (w == 0)     ? (c1.y - c1.x) : 0.5f * (c1.y - xl);
        gW_[1].y = 0.5f * (c1.z - c1.x);
        gW_[1].z = 0.5f * (c1.w - c1.y);
        gW_[1].w = (w + 4 == W) ? (c1.w - c1.z) : 0.5f * (xr - c1.z);
    }
}

// ---------------------------------------------------------------------------
// Flat energy kernel: one thread -> 2 d-adjacent quads (8 outputs).
template<int D, int H, int W>
__global__ void __launch_bounds__(256)
energy_flat(const float* __restrict__ def, const float* __restrict__ img,
            int scale_idx)
{
    constexpr int Wq = W >> 2;
    constexpr int D2n = D >> 1;
    constexpr int TOTAL = 2 * D2n * H * Wq;
    constexpr int VOL = D * H * W;
    int i = blockIdx.x * 256 + threadIdx.x;

    float local = 0.f;
    if (i < TOTAL) {
        int xq = i % Wq; int t = i / Wq;
        int h = t % H;    t /= H;
        int d2 = t % D2n;
        int n  = t / D2n;
        int w  = xq << 2;
        int d0 = d2 << 1;

        const float* base = def + n * 3 * VOL;

        float4 Exx[2], Eyy[2], Ezz[2], Sxy[2], Sxz[2], Syz[2], g2[2];
        {
            float4 gD[2], gH[2], gW[2];
            field_grads2<D, H, W>(base, d0, h, w, gD, gH, gW);      // u
            #pragma unroll
            for (int l = 0; l < 2; l++) { Exx[l] = gD[l]; Sxy[l] = gH[l]; Sxz[l] = gW[l]; }
        }
        {
            float4 gD[2], gH[2], gW[2];
            field_grads2<D, H, W>(base + VOL, d0, h, w, gD, gH, gW); // v
            #pragma unroll
            for (int l = 0; l < 2; l++) { Eyy[l] = gH[l]; Sxy[l] = f4add(Sxy[l], gD[l]); Syz[l] = gW[l]; }
        }
        {
            float4 gD[2], gH[2], gW[2];
            field_grads2<D, H, W>(base + 2 * VOL, d0, h, w, gD, gH, gW); // w
            #pragma unroll
            for (int l = 0; l < 2; l++) { Ezz[l] = gW[l]; Sxz[l] = f4add(Sxz[l], gD[l]); Syz[l] = f4add(Syz[l], gH[l]); }
        }
        {
            float4 gD[2], gH[2], gW[2];
            field_grads2<D, H, W>(img + n * VOL, d0, h, w, gD, gH, gW);
            #pragma unroll
            for (int l = 0; l < 2; l++) {
                g2[l].x = gD[l].x * gD[l].x + gH[l].x * gH[l].x + gW[l].x * gW[l].x;
                g2[l].y = gD[l].y * gD[l].y + gH[l].y * gH[l].y + gW[l].y * gW[l].y;
                g2[l].z = gD[l].z * gD[l].z + gH[l].z * gH[l].z + gW[l].z * gW[l].z;
                g2[l].w = gD[l].w * gD[l].w + gH[l].w * gH[l].w + gW[l].w * gW[l].w;
            }
        }

        #pragma unroll
        for (int l = 0; l < 2; l++) {
            const float* exx = reinterpret_cast<const float*>(&Exx[l]);
            const float* eyy = reinterpret_cast<const float*>(&Eyy[l]);
            const float* ezz = reinterpret_cast<const float*>(&Ezz[l]);
            const float* sxy = reinterpret_cast<const float*>(&Sxy[l]);
            const float* sxz = reinterpret_cast<const float*>(&Sxz[l]);
            const float* syz = reinterpret_cast<const float*>(&Syz[l]);
            const float* gg  = reinterpret_cast<const float*>(&g2[l]);
            #pragma unroll
            for (int j = 0; j < 4; j++) {
                float exy = 0.5f * sxy[j];
                float exz = 0.5f * sxz[j];
                float eyz = 0.5f * syz[j];
                float tr = exx[j] + eyy[j] + ezz[j];
                float g = sqrtf(gg[j]);
                float lam = 1.0f + 0.5f * g;
                float mu  = 1.0f + 0.5f * g;
                float e = 0.5f * lam * tr * tr
                        + mu * (exx[j] * exx[j] + eyy[j] * eyy[j] + ezz[j] * ezz[j]
                                + 2.0f * (exy * exy + exz * exz + eyz * eyz));
                local += (1.0f + 0.1f * g) * e;
            }
        }
    }

    #pragma unroll
    for (int o = 16; o > 0; o >>= 1)
        local += __shfl_down_sync(0xffffffffu, local, o);

    __shared__ float ws[8];
    int lane = threadIdx.x & 31;
    int wid  = threadIdx.x >> 5;
    if (lane == 0) ws[wid] = local;
    __syncthreads();
    if (wid == 0) {
        float s = (lane < 8) ? ws[lane] : 0.f;
        #pragma unroll
        for (int o = 4; o > 0; o >>= 1)
            s += __shfl_down_sync(0xffffffffu, s, o);
        if (lane == 0)
            atomicAdd(&g_acc[scale_idx], (double)s);
    }
}

// ---------------------------------------------------------------------------
__global__ void finalize_kernel(float* out) {
    double m0 = g_acc[0] / (2.0 * VOL0);
    double m1 = g_acc[1] / (2.0 * VOL1);
    double m2 = g_acc[2] / (2.0 * VOL2);
    out[0] = (float)(m0 + m1 + m2);
}

// ---------------------------------------------------------------------------
extern "C" void kernel_launch(void* const* d_in, const int* in_sizes, int n_in,
                              void* d_out, int out_size)
{
    const float* def = (const float*)d_in[0];
    const float* img = (const float*)d_in[1];
    float* out = (float*)d_out;

    float *p_def1, *p_img1, *p_def2, *p_img2;
    cudaGetSymbolAddress((void**)&p_def1, g_def1);
    cudaGetSymbolAddress((void**)&p_img1, g_img1);
    cudaGetSymbolAddress((void**)&p_def2, g_def2);
    cudaGetSymbolAddress((void**)&p_img2, g_img2);

    // Side stream + events, created once on the (uncaptured) correctness call.
    static cudaStream_t s_side = nullptr;
    static cudaEvent_t  s_fork = nullptr, s_join = nullptr;
    if (s_side == nullptr) {
        cudaStreamCreateWithFlags(&s_side, cudaStreamNonBlocking);
        cudaEventCreateWithFlags(&s_fork, cudaEventDisableTiming);
        cudaEventCreateWithFlags(&s_join, cudaEventDisableTiming);
    }

    init_acc_kernel<<<1, 32>>>();

    // Fork: scales 1 & 2 on the side stream, concurrent with scale 0.
    cudaEventRecord(s_fork, 0);
    cudaStreamWaitEvent(s_side, s_fork, 0);

    // ---- side stream: scale 1 then scale 2 ----
    {
        float rD = (float)((double)(D0 - 1) / (double)(D1 - 1));
        float rH = (float)((double)(H0 - 1) / (double)(H1 - 1));
        float rW = (float)((double)(W0 - 1) / (double)(W1 - 1));
        dim3 blk(W1, 3);
        dim3 grd(H1 / 3, D1, 8);
        downsample_both<D0, H0, W0, D1, H1, W1>
            <<<grd, blk, 0, s_side>>>(def, img, p_def1, p_img1, rD, rH, rW);

        constexpr int T1 = 2 * (D1 / 2) * H1 * (W1 / 4);
        energy_flat<D1, H1, W1><<<(T1 + 255) / 256, 256, 0, s_side>>>(p_def1, p_img1, 1);
    }
    {
        float rD = (float)((double)(D0 - 1) / (double)(D2 - 1));
        float rH = (float)((double)(H0 - 1) / (double)(H2 - 1));
        float rW = (float)((double)(W0 - 1) / (double)(W2 - 1));
        dim3 blk(W2, 6);
        dim3 grd(H2 / 6, D2, 8);
        downsample_both<D0, H0, W0, D2, H2, W2>
            <<<grd, blk, 0, s_side>>>(def, img, p_def2, p_img2, rD, rH, rW);

        constexpr int T2 = 2 * (D2 / 2) * H2 * (W2 / 4);
        energy_flat<D2, H2, W2><<<(T2 + 255) / 256, 256, 0, s_side>>>(p_def2, p_img2, 2);
    }

    // ---- main stream: scale 0 ----
    {
        constexpr int T0 = 2 * (D0 / 2) * H0 * (W0 / 4);
        energy_flat<D0, H0, W0><<<(T0 + 255) / 256, 256>>>(def, img, 0);
    }

    // Join, then finalize.
    cudaEventRecord(s_join, s_side);
    cudaStreamWaitEvent(0, s_join, 0);
    finalize_kernel<<<1, 1>>>(out);
}

// round 11
// speedup vs baseline: 1.0308x; 1.0308x over previous
#include <cuda_runtime.h>
#include <math.h>

// ---------------------------------------------------------------------------
// MultiScaleAdaptiveElasticityLossWithLame
//   d_in[0]: deformation_field (2,3,160,192,160) f32
//   d_in[1]: image             (2,1,160,192,160) f32
//   out: scalar f32 loss
// ---------------------------------------------------------------------------

#define D0 160
#define H0 192
#define W0 160
#define D1 80
#define H1 96
#define W1 80
#define D2 40
#define H2 48
#define W2 40

#define VOL0 (D0*H0*W0)
#define VOL1 (D1*H1*W1)
#define VOL2 (D2*H2*W2)

__device__ float g_def1[2*3*VOL1];
__device__ float g_img1[2*1*VOL1];
__device__ float g_def2[2*3*VOL2];
__device__ float g_img2[2*1*VOL2];
__device__ double g_acc[3];

__global__ void init_acc_kernel() {
    if (threadIdx.x < 3) g_acc[threadIdx.x] = 0.0;
}

// ---------------------------------------------------------------------------
// torch.gradient of one field at 4 consecutive W positions (R9-proven).
template<int D, int H, int W>
__device__ __forceinline__ void field_grads(const float* __restrict__ f,
                                            int d, int h, int w,
                                            float4& gD, float4& gH, float4& gW_)
{
    constexpr int sH = W;
    constexpr int sD = H * W;
    const float* base = f + d * sD + h * sH + w;

    float4 c = __ldg(reinterpret_cast<const float4*>(base));

    float xl = (w > 0)     ? __ldg(base - 1) : 0.f;
    float xr = (w + 4 < W) ? __ldg(base + 4) : 0.f;
    gW_.x = (w == 0)     ? (c.y - c.x) : 0.5f * (c.y - xl);
    gW_.y = 0.5f * (c.z - c.x);
    gW_.z = 0.5f * (c.w - c.y);
    gW_.w = (w + 4 == W) ? (c.w - c.z) : 0.5f * (xr - c.z);

    float4 hm = __ldg(reinterpret_cast<const float4*>(base - (h > 0     ? sH : 0)));
    float4 hp = __ldg(reinterpret_cast<const float4*>(base + (h < H - 1 ? sH : 0)));
    float sh = (h == 0 || h == H - 1) ? 1.0f : 0.5f;
    gH.x = sh * (hp.x - hm.x); gH.y = sh * (hp.y - hm.y);
    gH.z = sh * (hp.z - hm.z); gH.w = sh * (hp.w - hm.w);

    float4 dm = __ldg(reinterpret_cast<const float4*>(base - (d > 0     ? sD : 0)));
    float4 dp = __ldg(reinterpret_cast<const float4*>(base + (d < D - 1 ? sD : 0)));
    float sd = (d == 0 || d == D - 1) ? 1.0f : 0.5f;
    gD.x = sd * (dp.x - dm.x); gD.y = sd * (dp.y - dm.y);
    gD.z = sd * (dp.z - dm.z); gD.w = sd * (dp.w - dm.w);
}

__device__ __forceinline__ float4 f4add(float4 a, float4 b) {
    return make_float4(a.x + b.x, a.y + b.y, a.z + b.z, a.w + b.w);
}

// ---------------------------------------------------------------------------
// Energy body (R9-proven): one thread -> one quad; block reduction + atomic.
// bidx = logical block index within this energy sub-grid.
template<int D, int H, int W>
__device__ __forceinline__ void energy_body(const float* __restrict__ def,
                                            const float* __restrict__ img,
                                            int scale_idx, int bidx)
{
    constexpr int Wq = W >> 2;
    constexpr int TOTAL = 2 * D * H * Wq;
    constexpr int VOL = D * H * W;
    int i = bidx * 256 + threadIdx.x;

    float local = 0.f;
    if (i < TOTAL) {
        int xq = i % Wq; int t = i / Wq;
        int h = t % H;   t /= H;
        int d = t % D;
        int n = t / D;
        int w = xq << 2;

        const float* base = def + n * 3 * VOL;

        float4 Exx, Eyy, Ezz, Sxy, Sxz, Syz;   // Sab = 2*Eab
        {
            float4 gD, gH, gW;
            field_grads<D, H, W>(base, d, h, w, gD, gH, gW);   // u
            Exx = gD; Sxy = gH; Sxz = gW;
        }
        {
            float4 gD, gH, gW;
            field_grads<D, H, W>(base + VOL, d, h, w, gD, gH, gW);   // v
            Eyy = gH; Sxy = f4add(Sxy, gD); Syz = gW;
        }
        {
            float4 gD, gH, gW;
            field_grads<D, H, W>(base + 2 * VOL, d, h, w, gD, gH, gW);   // w
            Ezz = gW; Sxz = f4add(Sxz, gD); Syz = f4add(Syz, gH);
        }
        float4 g2;
        {
            float4 gD, gH, gW;
            field_grads<D, H, W>(img + n * VOL, d, h, w, gD, gH, gW);
            g2.x = gD.x * gD.x + gH.x * gH.x + gW.x * gW.x;
            g2.y = gD.y * gD.y + gH.y * gH.y + gW.y * gW.y;
            g2.z = gD.z * gD.z + gH.z * gH.z + gW.z * gW.z;
            g2.w = gD.w * gD.w + gH.w * gH.w + gW.w * gW.w;
        }

        const float* exx = reinterpret_cast<const float*>(&Exx);
        const float* eyy = reinterpret_cast<const float*>(&Eyy);
        const float* ezz = reinterpret_cast<const float*>(&Ezz);
        const float* sxy = reinterpret_cast<const float*>(&Sxy);
        const float* sxz = reinterpret_cast<const float*>(&Sxz);
        const float* syz = reinterpret_cast<const float*>(&Syz);
        const float* gg  = reinterpret_cast<const float*>(&g2);

        #pragma unroll
        for (int j = 0; j < 4; j++) {
            float exy = 0.5f * sxy[j];
            float exz = 0.5f * sxz[j];
            float eyz = 0.5f * syz[j];
            float tr = exx[j] + eyy[j] + ezz[j];
            float g = sqrtf(gg[j]);
            float lam = 1.0f + 0.5f * g;
            float mu  = 1.0f + 0.5f * g;
            float e = 0.5f * lam * tr * tr
                    + mu * (exx[j] * exx[j] + eyy[j] * eyy[j] + ezz[j] * ezz[j]
                            + 2.0f * (exy * exy + exz * exz + eyz * eyz));
            local += (1.0f + 0.1f * g) * e;
        }
    }

    #pragma unroll
    for (int o = 16; o > 0; o >>= 1)
        local += __shfl_down_sync(0xffffffffu, local, o);

    __shared__ float ws[8];
    int lane = threadIdx.x & 31;
    int wid  = threadIdx.x >> 5;
    if (lane == 0) ws[wid] = local;
    __syncthreads();
    if (wid == 0) {
        float s = (lane < 8) ? ws[lane] : 0.f;
        #pragma unroll
        for (int o = 4; o > 0; o >>= 1)
            s += __shfl_down_sync(0xffffffffu, s, o);
        if (lane == 0)
            atomicAdd(&g_acc[scale_idx], (double)s);
    }
}

// ---------------------------------------------------------------------------
// Trilinear downsample body (align_corners=True), flat index, one output per
// thread. planes: 0..5 = def channels, 6..7 = img.
template<int Di, int Hi, int Wi, int Do, int Ho, int Wo>
__device__ __forceinline__ void ds_body(const float* __restrict__ def,
                                        const float* __restrict__ img,
                                        float* __restrict__ odef,
                                        float* __restrict__ oimg,
                                        int bidx,
                                        float rD, float rH, float rW)
{
    constexpr int OVOL = Do * Ho * Wo;
    constexpr int IVOL = Di * Hi * Wi;
    int gid = bidx * 256 + threadIdx.x;

    int x = gid % Wo; int t = gid / Wo;
    int y = t % Ho;   t /= Ho;
    int z = t % Do;   int p = t / Do;      // 0..7

    const float* in; float* outp;
    if (p < 6) { in = def + p * IVOL;       outp = odef + p * OVOL; }
    else       { in = img + (p - 6) * IVOL; outp = oimg + (p - 6) * OVOL; }

    float cz = (float)z * rD;
    float cy = (float)y * rH;
    float cx = (float)x * rW;
    int z0 = min((int)floorf(cz), Di - 1);
    int y0 = min((int)floorf(cy), Hi - 1);
    int x0 = min((int)floorf(cx), Wi - 1);
    float wz = cz - (float)z0;
    float wy = cy - (float)y0;
    float wx = cx - (float)x0;
    int z1 = min(z0 + 1, Di - 1);
    int y1 = min(y0 + 1, Hi - 1);
    int x1 = min(x0 + 1, Wi - 1);

    const float* pz0 = in + z0 * (Hi * Wi);
    const float* pz1 = in + z1 * (Hi * Wi);
    int oy0 = y0 * Wi, oy1 = y1 * Wi;

    float v000 = __ldg(pz0 + oy0 + x0), v001 = __ldg(pz0 + oy0 + x1);
    float v010 = __ldg(pz0 + oy1 + x0), v011 = __ldg(pz0 + oy1 + x1);
    float v100 = __ldg(pz1 + oy0 + x0), v101 = __ldg(pz1 + oy0 + x1);
    float v110 = __ldg(pz1 + oy1 + x0), v111 = __ldg(pz1 + oy1 + x1);

    float a00 = v000 * (1.f - wx) + v001 * wx;
    float a01 = v010 * (1.f - wx) + v011 * wx;
    float a10 = v100 * (1.f - wx) + v101 * wx;
    float a11 = v110 * (1.f - wx) + v111 * wx;
    float b0 = a00 * (1.f - wy) + a01 * wy;
    float b1 = a10 * (1.f - wy) + a11 * wy;
    outp[z * (Ho * Wo) + y * Wo + x] = b0 * (1.f - wz) + b1 * wz;
}

// ---------------------------------------------------------------------------
// Phase A: e0 + ds1 + ds2 in one launch, roles striped by blockIdx.x % 13 so
// all three workloads are co-resident on every SM (latency-bound e0 overlaps
// DRAM-bound downsampling).
//   31200 blocks = 2400 groups of 13: [0..3]=e0, [4..11]=ds1, [12]=ds2.
#define E0_BLOCKS  9600   // 2*D0*H0*(W0/4)/256
#define DS1_BLOCKS 19200  // 8*VOL1/256
#define DS2_BLOCKS 2400   // 8*VOL2/256
#define A_BLOCKS   (E0_BLOCKS + DS1_BLOCKS + DS2_BLOCKS)

__global__ void __launch_bounds__(256)
mega_a(const float* __restrict__ def, const float* __restrict__ img,
       float r1D, float r1H, float r1W,
       float r2D, float r2H, float r2W)
{
    int grp = blockIdx.x / 13;
    int rol = blockIdx.x % 13;
    if (rol < 4) {
        energy_body<D0, H0, W0>(def, img, 0, grp * 4 + rol);
    } else if (rol < 12) {
        ds_body<D0, H0, W0, D1, H1, W1>(def, img, g_def1, g_img1,
                                        grp * 8 + (rol - 4), r1D, r1H, r1W);
    } else {
        ds_body<D0, H0, W0, D2, H2, W2>(def, img, g_def2, g_img2,
                                        grp, r2D, r2H, r2W);
    }
}

// Phase B: e1 + e2 (depends on Phase A's downsampled volumes).
#define E1_BLOCKS 1200    // 2*D1*H1*(W1/4)/256
#define E2_BLOCKS 150     // 2*D2*H2*(W2/4)/256
#define B_BLOCKS  (E1_BLOCKS + E2_BLOCKS)

__global__ void __launch_bounds__(256)
mega_b()
{
    if (blockIdx.x < E1_BLOCKS) {
        energy_body<D1, H1, W1>(g_def1, g_img1, 1, blockIdx.x);
    } else {
        energy_body<D2, H2, W2>(g_def2, g_img2, 2, blockIdx.x - E1_BLOCKS);
    }
}

// ---------------------------------------------------------------------------
__global__ void finalize_kernel(float* out) {
    double m0 = g_acc[0] / (2.0 * VOL0);
    double m1 = g_acc[1] / (2.0 * VOL1);
    double m2 = g_acc[2] / (2.0 * VOL2);
    out[0] = (float)(m0 + m1 + m2);
}

// ---------------------------------------------------------------------------
extern "C" void kernel_launch(void* const* d_in, const int* in_sizes, int n_in,
                              void* d_out, int out_size)
{
    const float* def = (const float*)d_in[0];
    const float* img = (const float*)d_in[1];
    float* out = (float*)d_out;

    float r1D = (float)((double)(D0 - 1) / (double)(D1 - 1));
    float r1H = (float)((double)(H0 - 1) / (double)(H1 - 1));
    float r1W = (float)((double)(W0 - 1) / (double)(W1 - 1));
    float r2D = (float)((double)(D0 - 1) / (double)(D2 - 1));
    float r2H = (float)((double)(H0 - 1) / (double)(H2 - 1));
    float r2W = (float)((double)(W0 - 1) / (double)(W2 - 1));

    init_acc_kernel<<<1, 32>>>();
    mega_a<<<A_BLOCKS, 256>>>(def, img, r1D, r1H, r1W, r2D, r2H, r2W);
    mega_b<<<B_BLOCKS, 256>>>();
    finalize_kernel<<<1, 1>>>(out);
}